// round 1
// baseline (speedup 1.0000x reference)
#include <cuda_runtime.h>
#include <math.h>

#define BB   2
#define QQ   2048
#define KLEN 2048
#define KP   2049
#define DD   512
#define NH   8
#define HD   64
#define SCALE_F   0.125f
#define NEG_INF_F -1e30f
#define LN_EPS_F  1e-5f

// ---------------- scratch (device globals; allocation-free) ----------------
__device__ float g_QN[BB * QQ * DD];
__device__ float g_KN[BB * KP * DD];
__device__ float g_VN[BB * KP * DD];
__device__ float g_QH[BB * QQ * DD];
__device__ float g_KH[BB * KP * DD];
__device__ float g_VH[BB * KP * DD];
__device__ float g_AV[BB * QQ * DD];
__device__ float g_AVO[BB * QQ * DD];

// ---------------- LayerNorm: one block (128 thr) per output row -------------
// Rows j >= rows_in_per_b are the appended all-zero row: LN(0) = beta.
__global__ void ln_kernel(const float* __restrict__ x,
                          const float* __restrict__ gamma,
                          const float* __restrict__ beta,
                          float* __restrict__ y,
                          int rows_in_per_b, int rows_out_per_b) {
    int r = blockIdx.x;
    int b = r / rows_out_per_b;
    int j = r - b * rows_out_per_b;
    int t = threadIdx.x;  // 128 threads, 4 floats each

    float4 g4 = ((const float4*)gamma)[t];
    float4 b4 = ((const float4*)beta)[t];
    float4* yr = (float4*)(y + (size_t)r * DD);

    if (j >= rows_in_per_b) { yr[t] = b4; return; }

    const float4* xr = (const float4*)(x + ((size_t)b * rows_in_per_b + j) * DD);
    float4 v = xr[t];
    float s  = v.x + v.y + v.z + v.w;
    float sq = v.x*v.x + v.y*v.y + v.z*v.z + v.w*v.w;
    #pragma unroll
    for (int o = 16; o > 0; o >>= 1) {
        s  += __shfl_xor_sync(0xffffffffu, s,  o);
        sq += __shfl_xor_sync(0xffffffffu, sq, o);
    }
    __shared__ float rs[4], rq[4];
    int w = t >> 5;
    if ((t & 31) == 0) { rs[w] = s; rq[w] = sq; }
    __syncthreads();
    s  = rs[0] + rs[1] + rs[2] + rs[3];
    sq = rq[0] + rq[1] + rq[2] + rq[3];

    float mean = s * (1.0f / DD);
    float var  = sq * (1.0f / DD) - mean * mean;
    float rstd = rsqrtf(var + LN_EPS_F);

    float4 o;
    o.x = (v.x - mean) * rstd * g4.x + b4.x;
    o.y = (v.y - mean) * rstd * g4.y + b4.y;
    o.z = (v.z - mean) * rstd * g4.z + b4.z;
    o.w = (v.w - mean) * rstd * g4.w + b4.w;
    yr[t] = o;
}

// ---------------- fp32 GEMM: C[M,512] = A[M,512] @ W[512,512] ---------------
// BM=64 BN=64 BK=32, 256 threads, 4x4 micro-tile per thread.
__global__ void __launch_bounds__(256) gemm512(const float* __restrict__ A,
                                               const float* __restrict__ W,
                                               float* __restrict__ C, int M) {
    __shared__ float As[32][64];   // k-major: As[k][m]
    __shared__ float Ws[32][64];   // k-major: Ws[k][n]
    int tid = threadIdx.x;
    int tx = tid & 15, ty = tid >> 4;
    int m0 = blockIdx.y * 64;
    int n0 = blockIdx.x * 64;
    float acc[4][4] = {};

    for (int k0 = 0; k0 < 512; k0 += 32) {
        #pragma unroll
        for (int it = 0; it < 2; it++) {
            int f = tid + it * 256;          // 0..511 float4 slots
            int row = f >> 3;                // 8 float4 per 32-wide row
            int kc  = (f & 7) << 2;
            int gm  = m0 + row;
            float4 v = (gm < M) ? *(const float4*)(A + (size_t)gm * 512 + k0 + kc)
                                : make_float4(0.f, 0.f, 0.f, 0.f);
            As[kc + 0][row] = v.x; As[kc + 1][row] = v.y;
            As[kc + 2][row] = v.z; As[kc + 3][row] = v.w;
        }
        #pragma unroll
        for (int it = 0; it < 2; it++) {
            int f = tid + it * 256;
            int row = f >> 4;                // 16 float4 per 64-wide row
            int nc  = (f & 15) << 2;
            *(float4*)&Ws[row][nc] =
                *(const float4*)(W + (size_t)(k0 + row) * 512 + n0 + nc);
        }
        __syncthreads();
        #pragma unroll
        for (int k = 0; k < 32; k++) {
            float4 a = *(float4*)&As[k][ty * 4];
            float4 w = *(float4*)&Ws[k][tx * 4];
            float av[4] = {a.x, a.y, a.z, a.w};
            float wv[4] = {w.x, w.y, w.z, w.w};
            #pragma unroll
            for (int i = 0; i < 4; i++)
                #pragma unroll
                for (int j = 0; j < 4; j++)
                    acc[i][j] += av[i] * wv[j];
        }
        __syncthreads();
    }
    #pragma unroll
    for (int i = 0; i < 4; i++) {
        int gm = m0 + ty * 4 + i;
        if (gm < M) {
            float4 o = make_float4(acc[i][0], acc[i][1], acc[i][2], acc[i][3]);
            *(float4*)(C + (size_t)gm * 512 + n0 + tx * 4) = o;
        }
    }
}

// ---------------- flash attention: one CTA per (b, h, 64-query tile) --------
__global__ void __launch_bounds__(256) attn_kernel(const float* __restrict__ QHp,
                                                   const float* __restrict__ KHp,
                                                   const float* __restrict__ VHp,
                                                   const int* __restrict__ kmask,
                                                   const int* __restrict__ qmask,
                                                   float* __restrict__ AV) {
    __shared__ float Qs[64 * 64];    // Q^T: Qs[d*64 + q]
    __shared__ float KPs[64 * 64];   // K^T: KPs[d*64 + j], reused as P^T[j*64 + q]
    __shared__ float Vs[64 * 64];    // V  : Vs[j*64 + d]

    int tid = threadIdx.x;
    int tx = tid & 15, ty = tid >> 4;
    int qb = blockIdx.x * 64;
    int h  = blockIdx.y;
    int b  = blockIdx.z;
    size_t qrow0 = (size_t)b * QQ + qb;

    // Load Q tile transposed (once)
    #pragma unroll
    for (int it = 0; it < 4; it++) {
        int f = tid + it * 256;          // 0..1023 float4
        int q = f >> 4;                  // 16 float4 per 64-d row
        int d = (f & 15) << 2;
        float4 v = *(const float4*)(QHp + (qrow0 + q) * DD + h * HD + d);
        Qs[(d + 0) * 64 + q] = v.x; Qs[(d + 1) * 64 + q] = v.y;
        Qs[(d + 2) * 64 + q] = v.z; Qs[(d + 3) * 64 + q] = v.w;
    }

    float mrow[4], lrow[4], O[4][4];
    #pragma unroll
    for (int i = 0; i < 4; i++) {
        mrow[i] = NEG_INF_F; lrow[i] = 0.f;
        #pragma unroll
        for (int j = 0; j < 4; j++) O[i][j] = 0.f;
    }

    for (int t0 = 0; t0 < KP; t0 += 64) {
        __syncthreads();   // previous P.V GEMM finished reading KPs/Vs
        #pragma unroll
        for (int it = 0; it < 4; it++) {
            int f = tid + it * 256;
            int j = f >> 4;
            int d = (f & 15) << 2;
            int jg = t0 + j;
            float4 kv = make_float4(0.f, 0.f, 0.f, 0.f);
            float4 vv = make_float4(0.f, 0.f, 0.f, 0.f);
            if (jg < KP) {
                size_t roff = ((size_t)b * KP + jg) * DD + h * HD + d;
                kv = *(const float4*)(KHp + roff);
                vv = *(const float4*)(VHp + roff);
            }
            KPs[(d + 0) * 64 + j] = kv.x; KPs[(d + 1) * 64 + j] = kv.y;
            KPs[(d + 2) * 64 + j] = kv.z; KPs[(d + 3) * 64 + j] = kv.w;
            *(float4*)&Vs[j * 64 + d] = vv;
        }
        __syncthreads();

        // S = Q K^T (4x4 per thread)
        float s[4][4] = {};
        #pragma unroll
        for (int d = 0; d < 64; d++) {
            float4 a = *(float4*)&Qs[d * 64 + ty * 4];
            float4 k = *(float4*)&KPs[d * 64 + tx * 4];
            float av[4] = {a.x, a.y, a.z, a.w};
            float kv[4] = {k.x, k.y, k.z, k.w};
            #pragma unroll
            for (int i = 0; i < 4; i++)
                #pragma unroll
                for (int j = 0; j < 4; j++)
                    s[i][j] += av[i] * kv[j];
        }

        // scale + key mask (appended slot j==KLEN is always valid)
        bool valid[4];
        #pragma unroll
        for (int j = 0; j < 4; j++) {
            int jg = t0 + tx * 4 + j;
            valid[j] = (jg < KP) && ((jg == KLEN) || (kmask[b * KLEN + jg] != 0));
        }
        #pragma unroll
        for (int i = 0; i < 4; i++)
            #pragma unroll
            for (int j = 0; j < 4; j++)
                s[i][j] = valid[j] ? s[i][j] * SCALE_F : NEG_INF_F;

        // online softmax (row reduce across tx via shfl, lanes 0..15 per ty)
        #pragma unroll
        for (int i = 0; i < 4; i++) {
            float mx = fmaxf(fmaxf(s[i][0], s[i][1]), fmaxf(s[i][2], s[i][3]));
            #pragma unroll
            for (int o = 8; o > 0; o >>= 1)
                mx = fmaxf(mx, __shfl_xor_sync(0xffffffffu, mx, o));
            float mn = fmaxf(mrow[i], mx);
            float alpha = __expf(mrow[i] - mn);
            float rsum = 0.f;
            #pragma unroll
            for (int j = 0; j < 4; j++) {
                float p = __expf(s[i][j] - mn);
                s[i][j] = p;
                rsum += p;
            }
            #pragma unroll
            for (int o = 8; o > 0; o >>= 1)
                rsum += __shfl_xor_sync(0xffffffffu, rsum, o);
            lrow[i] = lrow[i] * alpha + rsum;
            #pragma unroll
            for (int j = 0; j < 4; j++) O[i][j] *= alpha;
            mrow[i] = mn;
        }

        __syncthreads();   // done reading KPs as K^T
        // store P^T into KPs: P^T[j][q]
        #pragma unroll
        for (int i = 0; i < 4; i++)
            #pragma unroll
            for (int j = 0; j < 4; j++)
                KPs[(tx * 4 + j) * 64 + ty * 4 + i] = s[i][j];
        __syncthreads();

        // O += P V
        #pragma unroll
        for (int jj = 0; jj < 64; jj++) {
            float4 p = *(float4*)&KPs[jj * 64 + ty * 4];
            float4 v = *(float4*)&Vs[jj * 64 + tx * 4];
            float pv[4] = {p.x, p.y, p.z, p.w};
            float vv[4] = {v.x, v.y, v.z, v.w};
            #pragma unroll
            for (int i = 0; i < 4; i++)
                #pragma unroll
                for (int j = 0; j < 4; j++)
                    O[i][j] += pv[i] * vv[j];
        }
    }

    // epilogue: normalize, apply query mask, write AV
    #pragma unroll
    for (int i = 0; i < 4; i++) {
        int qg = qb + ty * 4 + i;
        float qm = (qmask[b * QQ + qg] != 0) ? 1.0f : 0.0f;
        float inv = qm / lrow[i];
        float4 o = make_float4(O[i][0] * inv, O[i][1] * inv,
                               O[i][2] * inv, O[i][3] * inv);
        *(float4*)(AV + (qrow0 + ty * 4 + i) * DD + h * HD + tx * 4) = o;
    }
}

// ---------------- g_net GEMM (K=1024 over [query | AVO]) + gated residual ---
__global__ void __launch_bounds__(256) gnet_gemm(const float* __restrict__ Aq,
                                                 const float* __restrict__ Av,
                                                 const float* __restrict__ GW,
                                                 const float* __restrict__ gb,
                                                 float* __restrict__ out) {
    __shared__ float As[32][64];
    __shared__ float Ws[32][64];
    int tid = threadIdx.x;
    int tx = tid & 15, ty = tid >> 4;
    int m0 = blockIdx.y * 64;
    int n0 = blockIdx.x * 64;
    float acc[4][4] = {};

    for (int k0 = 0; k0 < 1024; k0 += 32) {
        const float* A = (k0 < 512) ? Aq : Av;
        int kk = k0 & 511;
        #pragma unroll
        for (int it = 0; it < 2; it++) {
            int f = tid + it * 256;
            int row = f >> 3;
            int kc  = (f & 7) << 2;
            float4 v = *(const float4*)(A + (size_t)(m0 + row) * 512 + kk + kc);
            As[kc + 0][row] = v.x; As[kc + 1][row] = v.y;
            As[kc + 2][row] = v.z; As[kc + 3][row] = v.w;
        }
        #pragma unroll
        for (int it = 0; it < 2; it++) {
            int f = tid + it * 256;
            int row = f >> 4;
            int nc  = (f & 15) << 2;
            *(float4*)&Ws[row][nc] =
                *(const float4*)(GW + (size_t)(k0 + row) * 512 + n0 + nc);
        }
        __syncthreads();
        #pragma unroll
        for (int k = 0; k < 32; k++) {
            float4 a = *(float4*)&As[k][ty * 4];
            float4 w = *(float4*)&Ws[k][tx * 4];
            float av[4] = {a.x, a.y, a.z, a.w};
            float wv[4] = {w.x, w.y, w.z, w.w};
            #pragma unroll
            for (int i = 0; i < 4; i++)
                #pragma unroll
                for (int j = 0; j < 4; j++)
                    acc[i][j] += av[i] * wv[j];
        }
        __syncthreads();
    }

    float4 bb = *(const float4*)(gb + n0 + tx * 4);
    float bv[4] = {bb.x, bb.y, bb.z, bb.w};
    #pragma unroll
    for (int i = 0; i < 4; i++) {
        size_t gm = m0 + ty * 4 + i;
        float4 qv4 = *(const float4*)(Aq + gm * 512 + n0 + tx * 4);
        float4 av4 = *(const float4*)(Av + gm * 512 + n0 + tx * 4);
        float qv[4] = {qv4.x, qv4.y, qv4.z, qv4.w};
        float av[4] = {av4.x, av4.y, av4.z, av4.w};
        float o[4];
        #pragma unroll
        for (int j = 0; j < 4; j++) {
            float g = 1.0f / (1.0f + __expf(-(acc[i][j] + bv[j])));
            // out = q + g*q + (1-g)*av
            o[j] = qv[j] + g * qv[j] + (1.0f - g) * av[j];
        }
        *(float4*)(out + gm * 512 + n0 + tx * 4) =
            make_float4(o[0], o[1], o[2], o[3]);
    }
}

// ---------------- launch ----------------------------------------------------
extern "C" void kernel_launch(void* const* d_in, const int* in_sizes, int n_in,
                              void* d_out, int out_size) {
    const float* query = (const float*)d_in[0];
    const float* key   = (const float*)d_in[1];
    const float* value = (const float*)d_in[2];
    const float* wq    = (const float*)d_in[3];
    const float* wk    = (const float*)d_in[4];
    const float* wv    = (const float*)d_in[5];
    const float* wo    = (const float*)d_in[6];
    const float* gw    = (const float*)d_in[7];
    const float* gb    = (const float*)d_in[8];
    const float* qg    = (const float*)d_in[9];
    const float* qbv   = (const float*)d_in[10];
    const float* kg    = (const float*)d_in[11];
    const float* kbv   = (const float*)d_in[12];
    const float* vg    = (const float*)d_in[13];
    const float* vbv   = (const float*)d_in[14];
    const int* qmask   = (const int*)d_in[15];
    const int* kmask   = (const int*)d_in[16];
    float* out = (float*)d_out;

    float *QN, *KN, *VN, *QH, *KH, *VH, *AV, *AVO;
    cudaGetSymbolAddress((void**)&QN,  g_QN);
    cudaGetSymbolAddress((void**)&KN,  g_KN);
    cudaGetSymbolAddress((void**)&VN,  g_VN);
    cudaGetSymbolAddress((void**)&QH,  g_QH);
    cudaGetSymbolAddress((void**)&KH,  g_KH);
    cudaGetSymbolAddress((void**)&VH,  g_VH);
    cudaGetSymbolAddress((void**)&AV,  g_AV);
    cudaGetSymbolAddress((void**)&AVO, g_AVO);

    // 1) pre-layernorm (zero-append handled in-kernel: LN(0) = beta)
    ln_kernel<<<BB * QQ, 128>>>(query, qg, qbv, QN, QQ, QQ);
    ln_kernel<<<BB * KP, 128>>>(key,   kg, kbv, KN, KLEN, KP);
    ln_kernel<<<BB * KP, 128>>>(value, vg, vbv, VN, KLEN, KP);

    // 2) projections
    gemm512<<<dim3(8, 64), 256>>>(QN, wq, QH, BB * QQ);
    gemm512<<<dim3(8, 65), 256>>>(KN, wk, KH, BB * KP);
    gemm512<<<dim3(8, 65), 256>>>(VN, wv, VH, BB * KP);

    // 3) flash attention (writes query-masked attn_vec into AV)
    attn_kernel<<<dim3(QQ / 64, NH, BB), 256>>>(QH, KH, VH, kmask, qmask, AV);

    // 4) output projection
    gemm512<<<dim3(8, 64), 256>>>(AV, wo, AVO, BB * QQ);

    // 5) g_net + gated combination + residual -> d_out
    gnet_gemm<<<dim3(8, 64), 256>>>(query, AVO, gw, gb, out);
}